// round 8
// baseline (speedup 1.0000x reference)
#include <cuda_runtime.h>
#include <cuda_fp16.h>
#include <cstdint>

#define MAX_N   100000
#define MAX_E   1600000
#define NG      256
#define DHID    64
#define NBLK_MAX 128   // ceil(MAX_N/1024) = 98 < 128

// Scratch (allocation-free rule: __device__ globals).
__device__ uint2 g_bufA[(size_t)MAX_N * 16];     // fp16 64-wide rows: m1, later h2
__device__ uint2 g_bufB[(size_t)MAX_N * 16];     // fp16 64-wide rows: relu(h1)
__device__ float g_pool[NG * DHID];
__device__ float g_cnt[NG];
__device__ float g_wc[DHID * 16];                 // W3 @ Wlin (64x16)
__device__ int   g_is64;                          // 1 if indices are int64
__device__ int   g_deg[MAX_N];                    // in-degree histogram
__device__ int   g_rowptr[MAX_N + 1];             // CSR row pointers (by dst)
__device__ int   g_wptr[MAX_N];                   // fill cursors
__device__ __align__(16) int g_col[MAX_E];        // CSR: src node per edge slot
__device__ int   g_bsum[NBLK_MAX];                // per-block partial sums
__device__ int   g_boff[NBLK_MAX];                // exclusive block offsets

__device__ __forceinline__ int load_idx(const void* p, size_t i, int is64) {
    if (is64) return (int)(((const long long*)p)[i]);
    return ((const int*)p)[i];
}

// ---------------------------------------------------------------------------
// K1: block 0 detects index dtype (int64 values < 2^31 have zero odd words);
// other blocks zero g_deg, g_pool, g_cnt.
// ---------------------------------------------------------------------------
__global__ void init_kernel(const unsigned int* __restrict__ w, int n) {
    if (blockIdx.x == 0) {
        __shared__ unsigned int s;
        if (threadIdx.x == 0) s = 0u;
        __syncthreads();
        unsigned int v = 0u;
        for (int i = threadIdx.x; i < 1024; i += 256) v |= w[2 * i + 1];
        atomicOr(&s, v);
        __syncthreads();
        if (threadIdx.x == 0) g_is64 = (s == 0u) ? 1 : 0;
        return;
    }
    int t = (blockIdx.x - 1) * 256 + threadIdx.x;
    if (t < n) g_deg[t] = 0;
    float4 z = make_float4(0.f, 0.f, 0.f, 0.f);
    if (t < NG * 16) reinterpret_cast<float4*>(g_pool)[t] = z;
    if (t < NG / 4)  reinterpret_cast<float4*>(g_cnt)[t] = z;
}

// ---------------------------------------------------------------------------
// Dense matmul body (layer 1 only): out = fp16( A[n,128] @ W[128,64] )
// One 256-thread block handles 32 rows; thread: 2 rows x 4 cols.
// ---------------------------------------------------------------------------
__device__ __forceinline__ void mm_body128(const float* __restrict__ A,
                                           const float* __restrict__ W,
                                           uint2* __restrict__ out,
                                           int n, int bid) {
    constexpr int K = 128;
    __shared__ float  sx[32 * K];
    __shared__ float4 sw[K * 16];

    const int tid = threadIdx.x;
    const int rowbase = bid * 32;
    constexpr int K4 = K / 4;

    const float4* W4 = reinterpret_cast<const float4*>(W);
    #pragma unroll
    for (int i = tid; i < K * 16; i += 256) sw[i] = W4[i];

    const float4* A4 = reinterpret_cast<const float4*>(A);
    #pragma unroll
    for (int i = tid; i < 32 * K4; i += 256) {
        int r = i / K4, c = i % K4;
        int gr = rowbase + r;
        float4 v = make_float4(0.f, 0.f, 0.f, 0.f);
        if (gr < n) v = A4[(size_t)gr * K4 + c];
        reinterpret_cast<float4*>(sx)[i] = v;
    }
    __syncthreads();

    const int tcol = tid & 15;
    const int trow = tid >> 4;
    const int r0 = trow * 2, r1 = r0 + 1;

    float4 a0 = make_float4(0.f, 0.f, 0.f, 0.f);
    float4 a1 = make_float4(0.f, 0.f, 0.f, 0.f);

    const float4* sx4 = reinterpret_cast<const float4*>(sx);
    #pragma unroll
    for (int k4 = 0; k4 < K4; k4++) {
        float4 x0 = sx4[r0 * K4 + k4];
        float4 x1 = sx4[r1 * K4 + k4];
        #pragma unroll
        for (int kk = 0; kk < 4; kk++) {
            float e0 = (kk == 0) ? x0.x : (kk == 1) ? x0.y : (kk == 2) ? x0.z : x0.w;
            float e1 = (kk == 0) ? x1.x : (kk == 1) ? x1.y : (kk == 2) ? x1.z : x1.w;
            float4 w = sw[(k4 * 4 + kk) * 16 + tcol];
            a0.x = fmaf(e0, w.x, a0.x); a0.y = fmaf(e0, w.y, a0.y);
            a0.z = fmaf(e0, w.z, a0.z); a0.w = fmaf(e0, w.w, a0.w);
            a1.x = fmaf(e1, w.x, a1.x); a1.y = fmaf(e1, w.y, a1.y);
            a1.z = fmaf(e1, w.z, a1.z); a1.w = fmaf(e1, w.w, a1.w);
        }
    }

    int gr0 = rowbase + r0, gr1 = rowbase + r1;
    if (gr0 < n) {
        __half2 p0 = __floats2half2_rn(a0.x, a0.y);
        __half2 p1 = __floats2half2_rn(a0.z, a0.w);
        out[(size_t)gr0 * 16 + tcol] =
            make_uint2(*reinterpret_cast<unsigned*>(&p0), *reinterpret_cast<unsigned*>(&p1));
    }
    if (gr1 < n) {
        __half2 p0 = __floats2half2_rn(a1.x, a1.y);
        __half2 p1 = __floats2half2_rn(a1.z, a1.w);
        out[(size_t)gr1 * 16 + tcol] =
            make_uint2(*reinterpret_cast<unsigned*>(&p0), *reinterpret_cast<unsigned*>(&p1));
    }
}

// ---------------------------------------------------------------------------
// K2: fused independent work, partitioned by blockIdx:
//   [0, mmB)         : mm1  (x @ W1 -> fp16 bufA)
//   [mmB, +histB)    : dst histogram
//   [.., +cntB)      : per-graph node counts
//   last 4 blocks    : Wc = W3 @ Wlin
// ---------------------------------------------------------------------------
__global__ void __launch_bounds__(256) fused1_kernel(
    const float* __restrict__ x, const float* __restrict__ W1,
    uint2* __restrict__ outA,
    const float* __restrict__ W3, const float* __restrict__ Wlin,
    const void* __restrict__ ei, const void* __restrict__ bat,
    int n, int E, int mmB, int histB, int cntB)
{
    int b = blockIdx.x;
    if (b < mmB) {
        mm_body128(x, W1, outA, n, b);
        return;
    }
    b -= mmB;
    if (b < histB) {
        int e = b * 256 + threadIdx.x;
        if (e < E) {
            int d = load_idx(ei, (size_t)E + e, g_is64);
            atomicAdd(&g_deg[d], 1);
        }
        return;
    }
    b -= histB;
    if (b < cntB) {
        int t = b * 256 + threadIdx.x;
        if (t < n) {
            int g = load_idx(bat, (size_t)t, g_is64);
            atomicAdd(&g_cnt[g], 1.0f);
        }
        return;
    }
    b -= cntB;
    int t = b * 256 + threadIdx.x;
    if (t < DHID * 16) {
        int i = t >> 4, o = t & 15;
        float acc = 0.f;
        #pragma unroll
        for (int k = 0; k < 64; k++)
            acc = fmaf(W3[i * 64 + k], Wlin[k * 16 + o], acc);
        g_wc[t] = acc;
    }
}

// ---------------------------------------------------------------------------
// Scan stages for CSR rowptr.
// ---------------------------------------------------------------------------
__global__ void __launch_bounds__(256) blocksum_kernel(int n) {
    __shared__ int wsum[8];
    int tid = threadIdx.x;
    int base = blockIdx.x * 1024 + tid * 4;
    int s = 0;
    #pragma unroll
    for (int k = 0; k < 4; k++)
        if (base + k < n) s += g_deg[base + k];
    #pragma unroll
    for (int off = 16; off > 0; off >>= 1)
        s += __shfl_down_sync(0xffffffffu, s, off);
    if ((tid & 31) == 0) wsum[tid >> 5] = s;
    __syncthreads();
    if (tid == 0) {
        int t = 0;
        #pragma unroll
        for (int i = 0; i < 8; i++) t += wsum[i];
        g_bsum[blockIdx.x] = t;
    }
}

__global__ void __launch_bounds__(NBLK_MAX) scanbsum_kernel(int nblk) {
    __shared__ int s[NBLK_MAX];
    int tid = threadIdx.x;
    s[tid] = (tid < nblk) ? g_bsum[tid] : 0;
    __syncthreads();
    for (int off = 1; off < NBLK_MAX; off <<= 1) {
        int v = (tid >= off) ? s[tid - off] : 0;
        __syncthreads();
        s[tid] += v;
        __syncthreads();
    }
    if (tid < nblk) g_boff[tid] = (tid > 0) ? s[tid - 1] : 0;
}

__global__ void __launch_bounds__(256) writeptr_kernel(int n, int E) {
    __shared__ int tsum[256];
    int tid = threadIdx.x;
    int base = blockIdx.x * 1024 + tid * 4;
    int d[4];
    int s = 0;
    #pragma unroll
    for (int k = 0; k < 4; k++) {
        d[k] = (base + k < n) ? g_deg[base + k] : 0;
        s += d[k];
    }
    tsum[tid] = s;
    __syncthreads();
    for (int off = 1; off < 256; off <<= 1) {
        int v = (tid >= off) ? tsum[tid - off] : 0;
        __syncthreads();
        tsum[tid] += v;
        __syncthreads();
    }
    int run = ((tid > 0) ? tsum[tid - 1] : 0) + g_boff[blockIdx.x];
    #pragma unroll
    for (int k = 0; k < 4; k++) {
        if (base + k < n) {
            g_rowptr[base + k] = run;
            g_wptr[base + k]   = run;
            run += d[k];
        }
    }
    if (blockIdx.x == 0 && tid == 0) g_rowptr[n] = E;
}

__global__ void __launch_bounds__(256) fill_kernel(const void* __restrict__ ei, int E) {
    int e = blockIdx.x * blockDim.x + threadIdx.x;
    if (e >= E) return;
    int is64 = g_is64;
    int s = load_idx(ei, (size_t)e, is64);
    int d = load_idx(ei, (size_t)E + e, is64);
    int pos = atomicAdd(&g_wptr[d], 1);
    g_col[pos] = s;
}

// ---------------------------------------------------------------------------
// Gather core: aggregate fp16 rows of m over in-edges of `node`, lane j.
// ---------------------------------------------------------------------------
__device__ __forceinline__ void acc_u2(float4& acc, uint2 u) {
    float2 f0 = __half22float2(*reinterpret_cast<__half2*>(&u.x));
    float2 f1 = __half22float2(*reinterpret_cast<__half2*>(&u.y));
    acc.x += f0.x; acc.y += f0.y; acc.z += f1.x; acc.w += f1.y;
}

__device__ __forceinline__ float4 gather_core(const uint2* __restrict__ m,
                                              int node, int j) {
    int beg = g_rowptr[node];
    int end = g_rowptr[node + 1];
    float4 acc = make_float4(0.f, 0.f, 0.f, 0.f);

    int e = beg;
    int alim = (beg + 3) & ~3;
    if (alim > end) alim = end;
    for (; e < alim; e++)
        acc_u2(acc, m[(size_t)g_col[e] * 16 + j]);
    for (; e + 4 <= end; e += 4) {
        int4 s4 = *reinterpret_cast<const int4*>(g_col + e);
        uint2 u0 = m[(size_t)s4.x * 16 + j];
        uint2 u1 = m[(size_t)s4.y * 16 + j];
        uint2 u2 = m[(size_t)s4.z * 16 + j];
        uint2 u3 = m[(size_t)s4.w * 16 + j];
        acc_u2(acc, u0); acc_u2(acc, u1); acc_u2(acc, u2); acc_u2(acc, u3);
    }
    for (; e < end; e++)
        acc_u2(acc, m[(size_t)g_col[e] * 16 + j]);
    return acc;
}

// ---------------------------------------------------------------------------
// gather_kernel<MODE>: 16 lanes/node.
// MODE 1: out16[node] = fp16(relu(agg))            (layer 1 epilogue)
// MODE 2: g_pool[batch[node]] += agg               (layer 3 + pool)
// ---------------------------------------------------------------------------
template <int MODE>
__global__ void __launch_bounds__(256) gather_kernel(const uint2* __restrict__ m,
                                                     uint2* __restrict__ out16,
                                                     int n,
                                                     const void* __restrict__ batch) {
    int t = blockIdx.x * blockDim.x + threadIdx.x;
    int node = t >> 4;
    if (node >= n) return;
    int j = t & 15;

    float4 acc = gather_core(m, node, j);

    if (MODE == 1) {
        __half2 p0 = __floats2half2_rn(fmaxf(acc.x, 0.f), fmaxf(acc.y, 0.f));
        __half2 p1 = __floats2half2_rn(fmaxf(acc.z, 0.f), fmaxf(acc.w, 0.f));
        out16[(size_t)node * 16 + j] =
            make_uint2(*reinterpret_cast<unsigned*>(&p0), *reinterpret_cast<unsigned*>(&p1));
    } else {
        int b = load_idx(batch, (size_t)node, g_is64);
        float* dst = g_pool + b * 64 + j * 4;
        asm volatile("red.global.add.v4.f32 [%0], {%1,%2,%3,%4};"
                     :: "l"(dst), "f"(acc.x), "f"(acc.y), "f"(acc.z), "f"(acc.w)
                     : "memory");
    }
}

// ---------------------------------------------------------------------------
// Fused gather + GEMM (layer 2): out16[node] = fp16(relu( agg(m)[node] @ W2 )).
// Block = 256 threads = 16 nodes x 16 lanes. Aggregates into smem (stride 65
// to avoid bank conflicts), then applies W2 (staged in smem) in-block.
// ---------------------------------------------------------------------------
__global__ void __launch_bounds__(256) gatherW_kernel(const uint2* __restrict__ m,
                                                      const float* __restrict__ W2,
                                                      uint2* __restrict__ out16,
                                                      int n) {
    __shared__ float  sacc[16 * 65];     // 16 nodes x 64 feats, stride 65
    __shared__ float4 sw[64 * 16];       // W2 [64,64] as rows of 16 float4

    const int tid = threadIdx.x;
    const int nl = tid >> 4;             // node-local 0..15
    const int j = tid & 15;
    const int node = blockIdx.x * 16 + nl;

    // Stage W2.
    const float4* W4 = reinterpret_cast<const float4*>(W2);
    #pragma unroll
    for (int i = tid; i < 64 * 16; i += 256) sw[i] = W4[i];

    // Aggregate.
    if (node < n) {
        float4 acc = gather_core(m, node, j);
        float* row = sacc + nl * 65 + j * 4;
        row[0] = acc.x; row[1] = acc.y; row[2] = acc.z; row[3] = acc.w;
    }
    __syncthreads();

    // In-block GEMM: o[nl, j*4..j*4+3] = sum_k sacc[nl,k] * W2[k, j*4..]
    if (node < n) {
        const float* row = sacc + nl * 65;
        float4 o = make_float4(0.f, 0.f, 0.f, 0.f);
        #pragma unroll 16
        for (int k = 0; k < 64; k++) {
            float a = row[k];                    // broadcast within node group
            float4 w = sw[k * 16 + j];
            o.x = fmaf(a, w.x, o.x); o.y = fmaf(a, w.y, o.y);
            o.z = fmaf(a, w.z, o.z); o.w = fmaf(a, w.w, o.w);
        }
        __half2 p0 = __floats2half2_rn(fmaxf(o.x, 0.f), fmaxf(o.y, 0.f));
        __half2 p1 = __floats2half2_rn(fmaxf(o.z, 0.f), fmaxf(o.w, 0.f));
        out16[(size_t)node * 16 + j] =
            make_uint2(*reinterpret_cast<unsigned*>(&p0), *reinterpret_cast<unsigned*>(&p1));
    }
}

// ---------------------------------------------------------------------------
// Head: out[g,o] = (pool[g,:]/max(cnt,1)) @ Wc[:,o]   -> [256,16]
// ---------------------------------------------------------------------------
__global__ void final_kernel(float* __restrict__ out) {
    int t = blockIdx.x * blockDim.x + threadIdx.x;
    if (t >= NG * 16) return;
    int g = t >> 4, o = t & 15;
    float inv = 1.0f / fmaxf(g_cnt[g], 1.0f);
    float acc = 0.f;
    #pragma unroll
    for (int k = 0; k < 64; k++)
        acc = fmaf(g_pool[g * 64 + k], g_wc[k * 16 + o], acc);
    out[t] = acc * inv;
}

// ---------------------------------------------------------------------------
extern "C" void kernel_launch(void* const* d_in, const int* in_sizes, int n_in,
                              void* d_out, int out_size) {
    const float* x    = (const float*)d_in[0];
    const float* W1   = (const float*)d_in[1];
    const float* W2   = (const float*)d_in[2];
    const float* W3   = (const float*)d_in[3];
    const float* Wlin = (const float*)d_in[4];
    const void*  ei   = d_in[5];
    const void*  bat  = d_in[6];

    const int n = in_sizes[0] / 128;   // nodes
    const int E = in_sizes[5] / 2;     // edges

    uint2 *d_bufA, *d_bufB;
    cudaGetSymbolAddress((void**)&d_bufA, g_bufA);
    cudaGetSymbolAddress((void**)&d_bufB, g_bufB);

    const int mm_blocks  = (n + 31) / 32;
    const int e_blocks   = (E + 255) / 256;
    const int cnt_blocks = (n + 255) / 256;
    const int g_blocks   = (n * 16 + 255) / 256;
    const int gw_blocks  = (n + 15) / 16;
    const int nblk       = (n + 1023) / 1024;

    // K1: detect dtype + zero deg/pool/cnt.
    init_kernel<<<1 + cnt_blocks, 256>>>((const unsigned int*)ei, n);

    // K2: fused mm1 | hist | count | Wc.
    fused1_kernel<<<mm_blocks + e_blocks + cnt_blocks + 4, 256>>>(
        x, W1, d_bufA, W3, Wlin, ei, bat, n, E, mm_blocks, e_blocks, cnt_blocks);

    // CSR scan + fill.
    blocksum_kernel<<<nblk, 256>>>(n);
    scanbsum_kernel<<<1, NBLK_MAX>>>(nblk);
    writeptr_kernel<<<nblk, 256>>>(n, E);
    fill_kernel<<<e_blocks, 256>>>(ei, E);

    // Layer 1: r1 = fp16(relu(agg(m1)))
    gather_kernel<1><<<g_blocks, 256>>>(d_bufA, d_bufB, n, bat);

    // Layer 2 fused: h2 = fp16(relu( agg(r1) @ W2 ))
    gatherW_kernel<<<gw_blocks, 256>>>(d_bufB, W2, d_bufA, n);

    // Layer 3 + pool (linearity): pool[g] += agg(h2)[node]
    gather_kernel<2><<<g_blocks, 256>>>(d_bufA, nullptr, n, bat);

    // Head: out = (pool/cnt) @ (W3 @ Wlin)
    final_kernel<<<16, 256>>>((float*)d_out);
}

// round 9
// speedup vs baseline: 1.0822x; 1.0822x over previous
#include <cuda_runtime.h>
#include <cuda_fp16.h>
#include <cstdint>

#define MAX_N   100000
#define MAX_E   1600000
#define NG      256
#define DHID    64
#define NBLK_MAX 128   // ceil(MAX_N/1024) = 98 < 128

// Scratch (allocation-free rule: __device__ globals).
__device__ uint2 g_bufA[(size_t)MAX_N * 16];     // fp16 64-wide rows: m1, later h2
__device__ uint2 g_bufB[(size_t)MAX_N * 16];     // fp16 64-wide rows: relu(h1)
__device__ float g_h[(size_t)MAX_N * DHID];      // fp32: agg(r1)
__device__ float g_pool[NG * DHID];
__device__ float g_cnt[NG];
__device__ float g_wc[DHID * 16];                 // W3 @ Wlin (64x16)
__device__ int   g_is64;                          // 1 if indices are int64
__device__ int   g_deg[MAX_N];                    // in-degree histogram
__device__ int   g_rowptr[MAX_N + 1];             // CSR row pointers (by dst)
__device__ int   g_wptr[MAX_N];                   // fill cursors
__device__ __align__(16) int g_col[MAX_E];        // CSR: src node per edge slot
__device__ int   g_bsum[NBLK_MAX];                // per-block partial sums

__device__ __forceinline__ int load_idx(const void* p, size_t i, int is64) {
    if (is64) return (int)(((const long long*)p)[i]);
    return ((const int*)p)[i];
}

// ---------------------------------------------------------------------------
// K1: block 0 detects index dtype (int64 values < 2^31 have zero odd words);
// other blocks zero g_deg, g_pool, g_cnt.
// ---------------------------------------------------------------------------
__global__ void init_kernel(const unsigned int* __restrict__ w, int n) {
    if (blockIdx.x == 0) {
        __shared__ unsigned int s;
        if (threadIdx.x == 0) s = 0u;
        __syncthreads();
        unsigned int v = 0u;
        for (int i = threadIdx.x; i < 1024; i += 256) v |= w[2 * i + 1];
        atomicOr(&s, v);
        __syncthreads();
        if (threadIdx.x == 0) g_is64 = (s == 0u) ? 1 : 0;
        return;
    }
    int t = (blockIdx.x - 1) * 256 + threadIdx.x;
    if (t < n) g_deg[t] = 0;
    float4 z = make_float4(0.f, 0.f, 0.f, 0.f);
    if (t < NG * 16) reinterpret_cast<float4*>(g_pool)[t] = z;
    if (t < NG / 4)  reinterpret_cast<float4*>(g_cnt)[t] = z;
}

// ---------------------------------------------------------------------------
// Dense matmul body: out_fp16[n,64] = fp16( maybe_relu( A[n,K] @ W[K,64] ) )
// One 256-thread block handles 32 rows; thread: 2 rows x 4 cols.
// ---------------------------------------------------------------------------
template <int K, bool RELU_OUT>
__device__ __forceinline__ void mm_body(const float* __restrict__ A,
                                        const float* __restrict__ W,
                                        uint2* __restrict__ out,
                                        int n, int bid) {
    __shared__ float  sx[32 * K];
    __shared__ float4 sw[K * 16];

    const int tid = threadIdx.x;
    const int rowbase = bid * 32;
    constexpr int K4 = K / 4;

    const float4* W4 = reinterpret_cast<const float4*>(W);
    #pragma unroll
    for (int i = tid; i < K * 16; i += 256) sw[i] = W4[i];

    const float4* A4 = reinterpret_cast<const float4*>(A);
    #pragma unroll
    for (int i = tid; i < 32 * K4; i += 256) {
        int r = i / K4, c = i % K4;
        int gr = rowbase + r;
        float4 v = make_float4(0.f, 0.f, 0.f, 0.f);
        if (gr < n) v = A4[(size_t)gr * K4 + c];
        reinterpret_cast<float4*>(sx)[i] = v;
    }
    __syncthreads();

    const int tcol = tid & 15;
    const int trow = tid >> 4;
    const int r0 = trow * 2, r1 = r0 + 1;

    float4 a0 = make_float4(0.f, 0.f, 0.f, 0.f);
    float4 a1 = make_float4(0.f, 0.f, 0.f, 0.f);

    const float4* sx4 = reinterpret_cast<const float4*>(sx);
    #pragma unroll
    for (int k4 = 0; k4 < K4; k4++) {
        float4 x0 = sx4[r0 * K4 + k4];
        float4 x1 = sx4[r1 * K4 + k4];
        #pragma unroll
        for (int kk = 0; kk < 4; kk++) {
            float e0 = (kk == 0) ? x0.x : (kk == 1) ? x0.y : (kk == 2) ? x0.z : x0.w;
            float e1 = (kk == 0) ? x1.x : (kk == 1) ? x1.y : (kk == 2) ? x1.z : x1.w;
            float4 w = sw[(k4 * 4 + kk) * 16 + tcol];
            a0.x = fmaf(e0, w.x, a0.x); a0.y = fmaf(e0, w.y, a0.y);
            a0.z = fmaf(e0, w.z, a0.z); a0.w = fmaf(e0, w.w, a0.w);
            a1.x = fmaf(e1, w.x, a1.x); a1.y = fmaf(e1, w.y, a1.y);
            a1.z = fmaf(e1, w.z, a1.z); a1.w = fmaf(e1, w.w, a1.w);
        }
    }

    if (RELU_OUT) {
        a0.x = fmaxf(a0.x, 0.f); a0.y = fmaxf(a0.y, 0.f);
        a0.z = fmaxf(a0.z, 0.f); a0.w = fmaxf(a0.w, 0.f);
        a1.x = fmaxf(a1.x, 0.f); a1.y = fmaxf(a1.y, 0.f);
        a1.z = fmaxf(a1.z, 0.f); a1.w = fmaxf(a1.w, 0.f);
    }

    int gr0 = rowbase + r0, gr1 = rowbase + r1;
    if (gr0 < n) {
        __half2 p0 = __floats2half2_rn(a0.x, a0.y);
        __half2 p1 = __floats2half2_rn(a0.z, a0.w);
        out[(size_t)gr0 * 16 + tcol] =
            make_uint2(*reinterpret_cast<unsigned*>(&p0), *reinterpret_cast<unsigned*>(&p1));
    }
    if (gr1 < n) {
        __half2 p0 = __floats2half2_rn(a1.x, a1.y);
        __half2 p1 = __floats2half2_rn(a1.z, a1.w);
        out[(size_t)gr1 * 16 + tcol] =
            make_uint2(*reinterpret_cast<unsigned*>(&p0), *reinterpret_cast<unsigned*>(&p1));
    }
}

// Standalone matmul (layer 2).
template <int K, bool RELU_OUT>
__global__ void __launch_bounds__(256) mm_kernel(const float* __restrict__ A,
                                                 const float* __restrict__ W,
                                                 uint2* __restrict__ out,
                                                 int n) {
    mm_body<K, RELU_OUT>(A, W, out, n, blockIdx.x);
}

// ---------------------------------------------------------------------------
// K2: fused independent work, partitioned by blockIdx:
//   [0, mmB) : mm1 ; [mmB,+histB) : dst histogram ; [..,+cntB) : graph counts ;
//   last 4   : Wc = W3 @ Wlin
// ---------------------------------------------------------------------------
__global__ void __launch_bounds__(256) fused1_kernel(
    const float* __restrict__ x, const float* __restrict__ W1,
    uint2* __restrict__ outA,
    const float* __restrict__ W3, const float* __restrict__ Wlin,
    const void* __restrict__ ei, const void* __restrict__ bat,
    int n, int E, int mmB, int histB, int cntB)
{
    int b = blockIdx.x;
    if (b < mmB) {
        mm_body<128, false>(x, W1, outA, n, b);
        return;
    }
    b -= mmB;
    if (b < histB) {
        int e = b * 256 + threadIdx.x;
        if (e < E) {
            int d = load_idx(ei, (size_t)E + e, g_is64);
            atomicAdd(&g_deg[d], 1);
        }
        return;
    }
    b -= histB;
    if (b < cntB) {
        int t = b * 256 + threadIdx.x;
        if (t < n) {
            int g = load_idx(bat, (size_t)t, g_is64);
            atomicAdd(&g_cnt[g], 1.0f);
        }
        return;
    }
    b -= cntB;
    int t = b * 256 + threadIdx.x;
    if (t < DHID * 16) {
        int i = t >> 4, o = t & 15;
        float acc = 0.f;
        #pragma unroll
        for (int k = 0; k < 64; k++)
            acc = fmaf(W3[i * 64 + k], Wlin[k * 16 + o], acc);
        g_wc[t] = acc;
    }
}

// ---------------------------------------------------------------------------
// CSR scan stage 1: per-block sums over 1024-element chunks of g_deg.
// ---------------------------------------------------------------------------
__global__ void __launch_bounds__(256) blocksum_kernel(int n) {
    __shared__ int wsum[8];
    int tid = threadIdx.x;
    int base = blockIdx.x * 1024 + tid * 4;
    int s = 0;
    #pragma unroll
    for (int k = 0; k < 4; k++)
        if (base + k < n) s += g_deg[base + k];
    #pragma unroll
    for (int off = 16; off > 0; off >>= 1)
        s += __shfl_down_sync(0xffffffffu, s, off);
    if ((tid & 31) == 0) wsum[tid >> 5] = s;
    __syncthreads();
    if (tid == 0) {
        int t = 0;
        #pragma unroll
        for (int i = 0; i < 8; i++) t += wsum[i];
        g_bsum[blockIdx.x] = t;
    }
}

// ---------------------------------------------------------------------------
// CSR scan stage 2 (fused): each block sums its g_bsum prefix itself, then
// does the local rescan and writes rowptr/wptr. rowptr[n] = E analytically.
// ---------------------------------------------------------------------------
__global__ void __launch_bounds__(256) writeptr_kernel(int n, int E) {
    __shared__ int tsum[256];
    __shared__ int sboff;
    int tid = threadIdx.x;

    // Block-prefix: sum of g_bsum[0 .. blockIdx.x).
    {
        int partial = 0;
        for (int i = tid; i < blockIdx.x; i += 256) partial += g_bsum[i];
        #pragma unroll
        for (int off = 16; off > 0; off >>= 1)
            partial += __shfl_down_sync(0xffffffffu, partial, off);
        __shared__ int wsum[8];
        if ((tid & 31) == 0) wsum[tid >> 5] = partial;
        __syncthreads();
        if (tid == 0) {
            int t = 0;
            #pragma unroll
            for (int i = 0; i < 8; i++) t += wsum[i];
            sboff = t;
        }
    }

    int base = blockIdx.x * 1024 + tid * 4;
    int d[4];
    int s = 0;
    #pragma unroll
    for (int k = 0; k < 4; k++) {
        d[k] = (base + k < n) ? g_deg[base + k] : 0;
        s += d[k];
    }
    tsum[tid] = s;
    __syncthreads();
    for (int off = 1; off < 256; off <<= 1) {
        int v = (tid >= off) ? tsum[tid - off] : 0;
        __syncthreads();
        tsum[tid] += v;
        __syncthreads();
    }
    int run = ((tid > 0) ? tsum[tid - 1] : 0) + sboff;
    #pragma unroll
    for (int k = 0; k < 4; k++) {
        if (base + k < n) {
            g_rowptr[base + k] = run;
            g_wptr[base + k]   = run;
            run += d[k];
        }
    }
    if (blockIdx.x == 0 && tid == 0) g_rowptr[n] = E;
}

__global__ void __launch_bounds__(256) fill_kernel(const void* __restrict__ ei, int E) {
    int e = blockIdx.x * blockDim.x + threadIdx.x;
    if (e >= E) return;
    int is64 = g_is64;
    int s = load_idx(ei, (size_t)e, is64);
    int d = load_idx(ei, (size_t)E + e, is64);
    int pos = atomicAdd(&g_wptr[d], 1);
    g_col[pos] = s;
}

// ---------------------------------------------------------------------------
// Gather core: aggregate fp16 rows over in-edges of `node`, lane j.
// 4-edge unroll sums in half2 via a depth-2 HADD2 tree, converting once per
// group to fp32 (cuts per-edge instruction count ~2x vs per-edge converts).
// ---------------------------------------------------------------------------
__device__ __forceinline__ __half2 u2h(unsigned u) {
    return *reinterpret_cast<__half2*>(&u);
}

__device__ __forceinline__ void acc_u2(float4& acc, uint2 u) {
    float2 f0 = __half22float2(u2h(u.x));
    float2 f1 = __half22float2(u2h(u.y));
    acc.x += f0.x; acc.y += f0.y; acc.z += f1.x; acc.w += f1.y;
}

__device__ __forceinline__ float4 gather_core(const uint2* __restrict__ m,
                                              int node, int j) {
    int beg = g_rowptr[node];
    int end = g_rowptr[node + 1];
    float4 acc = make_float4(0.f, 0.f, 0.f, 0.f);

    int e = beg;
    int alim = (beg + 3) & ~3;
    if (alim > end) alim = end;
    for (; e < alim; e++)
        acc_u2(acc, m[(size_t)g_col[e] * 16 + j]);

    for (; e + 4 <= end; e += 4) {
        int4 s4 = *reinterpret_cast<const int4*>(g_col + e);
        uint2 u0 = m[(size_t)s4.x * 16 + j];
        uint2 u1 = m[(size_t)s4.y * 16 + j];
        uint2 u2 = m[(size_t)s4.z * 16 + j];
        uint2 u3 = m[(size_t)s4.w * 16 + j];
        // Depth-2 half2 tree, one fp32 conversion per 4 edges.
        __half2 a = __hadd2(__hadd2(u2h(u0.x), u2h(u1.x)),
                            __hadd2(u2h(u2.x), u2h(u3.x)));
        __half2 b = __hadd2(__hadd2(u2h(u0.y), u2h(u1.y)),
                            __hadd2(u2h(u2.y), u2h(u3.y)));
        float2 f0 = __half22float2(a);
        float2 f1 = __half22float2(b);
        acc.x += f0.x; acc.y += f0.y; acc.z += f1.x; acc.w += f1.y;
    }
    for (; e < end; e++)
        acc_u2(acc, m[(size_t)g_col[e] * 16 + j]);
    return acc;
}

// ---------------------------------------------------------------------------
// gather_kernel<MODE>: 16 lanes/node.
// MODE 0: g_h[node] = agg (fp32)                    (layer 2 input)
// MODE 1: out16[node] = fp16(relu(agg))             (layer 1 epilogue)
// MODE 2: g_pool[batch[node]] += agg                (layer 3 + pool)
// ---------------------------------------------------------------------------
template <int MODE>
__global__ void __launch_bounds__(256) gather_kernel(const uint2* __restrict__ m,
                                                     uint2* __restrict__ out16,
                                                     int n,
                                                     const void* __restrict__ batch) {
    int t = blockIdx.x * blockDim.x + threadIdx.x;
    int node = t >> 4;
    if (node >= n) return;
    int j = t & 15;

    float4 acc = gather_core(m, node, j);

    if (MODE == 0) {
        reinterpret_cast<float4*>(g_h)[(size_t)node * 16 + j] = acc;
    } else if (MODE == 1) {
        __half2 p0 = __floats2half2_rn(fmaxf(acc.x, 0.f), fmaxf(acc.y, 0.f));
        __half2 p1 = __floats2half2_rn(fmaxf(acc.z, 0.f), fmaxf(acc.w, 0.f));
        out16[(size_t)node * 16 + j] =
            make_uint2(*reinterpret_cast<unsigned*>(&p0), *reinterpret_cast<unsigned*>(&p1));
    } else {
        int b = load_idx(batch, (size_t)node, g_is64);
        float* dst = g_pool + b * 64 + j * 4;
        asm volatile("red.global.add.v4.f32 [%0], {%1,%2,%3,%4};"
                     :: "l"(dst), "f"(acc.x), "f"(acc.y), "f"(acc.z), "f"(acc.w)
                     : "memory");
    }
}

// ---------------------------------------------------------------------------
// Head: out[g,o] = (pool[g,:]/max(cnt,1)) @ Wc[:,o]   -> [256,16]
// ---------------------------------------------------------------------------
__global__ void final_kernel(float* __restrict__ out) {
    int t = blockIdx.x * blockDim.x + threadIdx.x;
    if (t >= NG * 16) return;
    int g = t >> 4, o = t & 15;
    float inv = 1.0f / fmaxf(g_cnt[g], 1.0f);
    float acc = 0.f;
    #pragma unroll
    for (int k = 0; k < 64; k++)
        acc = fmaf(g_pool[g * 64 + k], g_wc[k * 16 + o], acc);
    out[t] = acc * inv;
}

// ---------------------------------------------------------------------------
extern "C" void kernel_launch(void* const* d_in, const int* in_sizes, int n_in,
                              void* d_out, int out_size) {
    const float* x    = (const float*)d_in[0];
    const float* W1   = (const float*)d_in[1];
    const float* W2   = (const float*)d_in[2];
    const float* W3   = (const float*)d_in[3];
    const float* Wlin = (const float*)d_in[4];
    const void*  ei   = d_in[5];
    const void*  bat  = d_in[6];

    const int n = in_sizes[0] / 128;   // nodes
    const int E = in_sizes[5] / 2;     // edges

    float* d_h;
    uint2 *d_bufA, *d_bufB;
    cudaGetSymbolAddress((void**)&d_h,    g_h);
    cudaGetSymbolAddress((void**)&d_bufA, g_bufA);
    cudaGetSymbolAddress((void**)&d_bufB, g_bufB);

    const int mm_blocks  = (n + 31) / 32;
    const int e_blocks   = (E + 255) / 256;
    const int cnt_blocks = (n + 255) / 256;
    const int g_blocks   = (n * 16 + 255) / 256;
    const int nblk       = (n + 1023) / 1024;

    // K1: detect dtype + zero deg/pool/cnt.
    init_kernel<<<1 + cnt_blocks, 256>>>((const unsigned int*)ei, n);

    // K2: fused mm1 | hist | count | Wc.
    fused1_kernel<<<mm_blocks + e_blocks + cnt_blocks + 4, 256>>>(
        x, W1, d_bufA, W3, Wlin, ei, bat, n, E, mm_blocks, e_blocks, cnt_blocks);

    // CSR scan (2 stages) + fill.
    blocksum_kernel<<<nblk, 256>>>(n);
    writeptr_kernel<<<nblk, 256>>>(n, E);
    fill_kernel<<<e_blocks, 256>>>(ei, E);

    // Layer 1: r1 = fp16(relu(agg(m1)))
    gather_kernel<1><<<g_blocks, 256>>>(d_bufA, d_bufB, n, bat);

    // Layer 2: t2 = agg(r1); h2 = fp16(relu(t2 @ W2))
    gather_kernel<0><<<g_blocks, 256>>>(d_bufB, nullptr, n, bat);
    mm_kernel<64, true><<<mm_blocks, 256>>>(d_h, W2, d_bufA, n);

    // Layer 3 + pool (linearity): pool[g] += agg(h2)[node]
    gather_kernel<2><<<g_blocks, 256>>>(d_bufA, nullptr, n, bat);

    // Head: out = (pool/cnt) @ (W3 @ Wlin)
    final_kernel<<<16, 256>>>((float*)d_out);
}